// round 7
// baseline (speedup 1.0000x reference)
#include <cuda_runtime.h>
#include <math.h>

// Problem constants
constexpr int Bc = 2;
constexpr int Tc = 2048;
constexpr int Cc = 1024;
constexpr int Hc = 16;
constexpr int HDc = 64;
constexpr int Mc = Bc * Tc;  // 4096 rows

// Scratch (allocation-free rule: __device__ globals)
__device__ float g_q[Bc * Tc * Cc];
__device__ float g_k[Bc * Tc * Cc];
__device__ float g_v[Bc * Tc * Cc];
__device__ float g_att[Bc * Tc * Cc];

// ---------------------------------------------------------------------------
// GEMM: Cm[m,n] = sum_k A[m*K+k] * W[n*K+k]   (A: MxK row-major, W: NxK row-major)
// 128x128 block tile, 256 threads, 8x8 microtile, K-step 8, reg prefetch.
// Smem stride 132 (mod 32 = 4) -> conflict-free loads and stores.
// ---------------------------------------------------------------------------
constexpr int GLDS = 132;

__global__ __launch_bounds__(256) void gemm_nt(
    const float* __restrict__ A, const float* __restrict__ W,
    float* __restrict__ Cm, int Mdim, int Ndim, int Kdim)
{
    __shared__ float As[8 * GLDS];
    __shared__ float Bs[8 * GLDS];

    const int tid = threadIdx.x;
    const int tx = tid & 15;        // 0..15 (N microtiles)
    const int ty = tid >> 4;        // 0..15 (M microtiles)
    const int bm = blockIdx.y * 128;
    const int bn = blockIdx.x * 128;

    const int lr = tid >> 1;        // 0..127 tile row to load
    const int lk = (tid & 1) * 4;   // k offset (float4)
    const float* Ap = A + (size_t)(bm + lr) * Kdim + lk;
    const float* Bp = W + (size_t)(bn + lr) * Kdim + lk;

    float4 a4 = *(const float4*)Ap;
    float4 b4 = *(const float4*)Bp;

    float acc[8][8];
#pragma unroll
    for (int i = 0; i < 8; i++)
#pragma unroll
        for (int j = 0; j < 8; j++) acc[i][j] = 0.f;

    for (int k0 = 0; k0 < Kdim; k0 += 8) {
        As[(lk + 0) * GLDS + lr] = a4.x;
        As[(lk + 1) * GLDS + lr] = a4.y;
        As[(lk + 2) * GLDS + lr] = a4.z;
        As[(lk + 3) * GLDS + lr] = a4.w;
        Bs[(lk + 0) * GLDS + lr] = b4.x;
        Bs[(lk + 1) * GLDS + lr] = b4.y;
        Bs[(lk + 2) * GLDS + lr] = b4.z;
        Bs[(lk + 3) * GLDS + lr] = b4.w;
        __syncthreads();

        if (k0 + 8 < Kdim) {            // prefetch next K-slab (latency overlap)
            a4 = *(const float4*)(Ap + k0 + 8);
            b4 = *(const float4*)(Bp + k0 + 8);
        }

#pragma unroll
        for (int k = 0; k < 8; k++) {
            float4 ar0 = *(const float4*)&As[k * GLDS + ty * 8];
            float4 ar1 = *(const float4*)&As[k * GLDS + ty * 8 + 4];
            float4 br0 = *(const float4*)&Bs[k * GLDS + tx * 8];
            float4 br1 = *(const float4*)&Bs[k * GLDS + tx * 8 + 4];
            float ar[8] = {ar0.x, ar0.y, ar0.z, ar0.w, ar1.x, ar1.y, ar1.z, ar1.w};
            float br[8] = {br0.x, br0.y, br0.z, br0.w, br1.x, br1.y, br1.z, br1.w};
#pragma unroll
            for (int i = 0; i < 8; i++)
#pragma unroll
                for (int j = 0; j < 8; j++)
                    acc[i][j] = fmaf(ar[i], br[j], acc[i][j]);
        }
        __syncthreads();
    }

#pragma unroll
    for (int i = 0; i < 8; i++) {
        float* dst = Cm + (size_t)(bm + ty * 8 + i) * Ndim + bn + tx * 8;
        *(float4*)dst       = make_float4(acc[i][0], acc[i][1], acc[i][2], acc[i][3]);
        *(float4*)(dst + 4) = make_float4(acc[i][4], acc[i][5], acc[i][6], acc[i][7]);
    }
}

// ---------------------------------------------------------------------------
// RoPE applied in-place to Q and K. One thread per (b,t,h,i) pair, i in [0,32).
// Pairs are interleaved elements (2i, 2i+1) of each 64-dim head.
// ---------------------------------------------------------------------------
__global__ __launch_bounds__(256) void rope_kernel(
    float* __restrict__ q, float* __restrict__ k,
    const float* __restrict__ cosp, const float* __restrict__ sinp)
{
    int idx = blockIdx.x * blockDim.x + threadIdx.x;  // exactly B*T*H*32 threads
    int i = idx & 31;
    int h = (idx >> 5) & (Hc - 1);
    int t = (idx >> 9) & (Tc - 1);
    int b = idx >> 20;

    float c = cosp[t * 32 + i];
    float s = sinp[t * 32 + i];
    size_t base = ((size_t)(b * Tc + t)) * Cc + h * HDc + 2 * i;

    float2* qp = (float2*)(q + base);
    float2 qq = *qp;
    *qp = make_float2(qq.x * c - qq.y * s, qq.x * s + qq.y * c);

    float2* kp = (float2*)(k + base);
    float2 kk = *kp;
    *kp = make_float2(kk.x * c - kk.y * s, kk.x * s + kk.y * c);
}

// ---------------------------------------------------------------------------
// Causal flash attention, fp32. Block = (qtile 64 rows, head, batch).
// 256 threads, each owns a 4x4 microtile of the 64x64 score / output tiles.
// Smem: Qst (d-major), Kst (d-major, aliased by P col-major), Vs (j-major),
// all with row stride 68 (mod 32 = 4) -> conflict-free inner-loop LDS.128.
// Only the causal lower triangle of key tiles is visited.
// ---------------------------------------------------------------------------
constexpr int ALD = 68;
constexpr int ATTN_SMEM = 3 * 64 * ALD * (int)sizeof(float);  // 52224 B

__global__ __launch_bounds__(256) void attn_kernel(
    const float* __restrict__ Q, const float* __restrict__ K,
    const float* __restrict__ V, float* __restrict__ O)
{
    extern __shared__ float sm[];
    float* Qst = sm;                  // [d][r]
    float* Kst = sm + 64 * ALD;       // [d][j]; aliased as P [col][row] after scores
    float* Vs  = sm + 2 * 64 * ALD;   // [j][dd]

    const int tid = threadIdx.x;
    const int tx = tid & 15;   // key-col / out-dim microtile
    const int ty = tid >> 4;   // query-row microtile
    const int qt = blockIdx.x;
    const int h  = blockIdx.y;
    const int b  = blockIdx.z;
    const int q0 = qt * 64;

    const int lr  = tid >> 2;         // 0..63 row to load
    const int ld0 = (tid & 3) * 16;   // dim offset

    // Load Q tile transposed (d-major)
    {
        const float* src = Q + (size_t)(b * Tc + q0 + lr) * Cc + h * HDc + ld0;
#pragma unroll
        for (int c4 = 0; c4 < 4; c4++) {
            float4 v4 = *(const float4*)(src + c4 * 4);
            Qst[(ld0 + c4 * 4 + 0) * ALD + lr] = v4.x;
            Qst[(ld0 + c4 * 4 + 1) * ALD + lr] = v4.y;
            Qst[(ld0 + c4 * 4 + 2) * ALD + lr] = v4.z;
            Qst[(ld0 + c4 * 4 + 3) * ALD + lr] = v4.w;
        }
    }

    float m_i[4], l_i[4], acc[4][4];
#pragma unroll
    for (int i = 0; i < 4; i++) {
        m_i[i] = -1e30f;
        l_i[i] = 0.f;
#pragma unroll
        for (int j = 0; j < 4; j++) acc[i][j] = 0.f;
    }

    for (int kt = 0; kt <= qt; kt++) {
        __syncthreads();  // protects Qst(first iter) + prior P/V reads
        {
            const float* ks = K + (size_t)(b * Tc + kt * 64 + lr) * Cc + h * HDc + ld0;
            const float* vs = V + (size_t)(b * Tc + kt * 64 + lr) * Cc + h * HDc + ld0;
#pragma unroll
            for (int c4 = 0; c4 < 4; c4++) {
                float4 kv = *(const float4*)(ks + c4 * 4);
                Kst[(ld0 + c4 * 4 + 0) * ALD + lr] = kv.x;
                Kst[(ld0 + c4 * 4 + 1) * ALD + lr] = kv.y;
                Kst[(ld0 + c4 * 4 + 2) * ALD + lr] = kv.z;
                Kst[(ld0 + c4 * 4 + 3) * ALD + lr] = kv.w;
                float4 vv = *(const float4*)(vs + c4 * 4);
                *(float4*)&Vs[lr * ALD + ld0 + c4 * 4] = vv;
            }
        }
        __syncthreads();

        // S = Q K^T (4x4 microtile per thread)
        float s[4][4];
#pragma unroll
        for (int i = 0; i < 4; i++)
#pragma unroll
            for (int j = 0; j < 4; j++) s[i][j] = 0.f;

#pragma unroll 8
        for (int d = 0; d < 64; d++) {
            float4 aq = *(const float4*)&Qst[d * ALD + ty * 4];
            float4 bk = *(const float4*)&Kst[d * ALD + tx * 4];
            float ar[4] = {aq.x, aq.y, aq.z, aq.w};
            float br[4] = {bk.x, bk.y, bk.z, bk.w};
#pragma unroll
            for (int i = 0; i < 4; i++)
#pragma unroll
                for (int j = 0; j < 4; j++)
                    s[i][j] = fmaf(ar[i], br[j], s[i][j]);
        }

        const float scale = 0.125f;  // 1/sqrt(64)
        if (kt == qt) {
#pragma unroll
            for (int i = 0; i < 4; i++)
#pragma unroll
                for (int j = 0; j < 4; j++) {
                    int qr = ty * 4 + i, kc = tx * 4 + j;
                    s[i][j] = (kc <= qr) ? s[i][j] * scale : -1e30f;
                }
        } else {
#pragma unroll
            for (int i = 0; i < 4; i++)
#pragma unroll
                for (int j = 0; j < 4; j++) s[i][j] *= scale;
        }

        // Online softmax (row stats shared across the 16 lanes of each ty half)
        float p[4][4];
#pragma unroll
        for (int i = 0; i < 4; i++) {
            float rm = fmaxf(fmaxf(s[i][0], s[i][1]), fmaxf(s[i][2], s[i][3]));
            rm = fmaxf(rm, __shfl_xor_sync(0xffffffffu, rm, 1));
            rm = fmaxf(rm, __shfl_xor_sync(0xffffffffu, rm, 2));
            rm = fmaxf(rm, __shfl_xor_sync(0xffffffffu, rm, 4));
            rm = fmaxf(rm, __shfl_xor_sync(0xffffffffu, rm, 8));
            float mnew = fmaxf(m_i[i], rm);
            float f = __expf(m_i[i] - mnew);
            float rs = 0.f;
#pragma unroll
            for (int j = 0; j < 4; j++) {
                p[i][j] = __expf(s[i][j] - mnew);
                rs += p[i][j];
            }
            rs += __shfl_xor_sync(0xffffffffu, rs, 1);
            rs += __shfl_xor_sync(0xffffffffu, rs, 2);
            rs += __shfl_xor_sync(0xffffffffu, rs, 4);
            rs += __shfl_xor_sync(0xffffffffu, rs, 8);
            l_i[i] = l_i[i] * f + rs;
            m_i[i] = mnew;
#pragma unroll
            for (int j = 0; j < 4; j++) acc[i][j] *= f;
        }

        __syncthreads();  // done reading Kst; safe to alias with P
        float* Pst = Kst; // [col][row]
#pragma unroll
        for (int j = 0; j < 4; j++) {
            *(float4*)&Pst[(tx * 4 + j) * ALD + ty * 4] =
                make_float4(p[0][j], p[1][j], p[2][j], p[3][j]);
        }
        __syncthreads();

        // O += P V
#pragma unroll 8
        for (int j = 0; j < 64; j++) {
            float4 ap = *(const float4*)&Pst[j * ALD + ty * 4];
            float4 bv = *(const float4*)&Vs[j * ALD + tx * 4];
            float ar[4] = {ap.x, ap.y, ap.z, ap.w};
            float br[4] = {bv.x, bv.y, bv.z, bv.w};
#pragma unroll
            for (int i = 0; i < 4; i++)
#pragma unroll
                for (int jj = 0; jj < 4; jj++)
                    acc[i][jj] = fmaf(ar[i], br[jj], acc[i][jj]);
        }
    }

    // Normalize + write
#pragma unroll
    for (int i = 0; i < 4; i++) {
        float inv = 1.f / l_i[i];
        float* dst = O + (size_t)(b * Tc + q0 + ty * 4 + i) * Cc + h * HDc + tx * 4;
        *(float4*)dst = make_float4(acc[i][0] * inv, acc[i][1] * inv,
                                    acc[i][2] * inv, acc[i][3] * inv);
    }
}

// ---------------------------------------------------------------------------
// Launch: QKV GEMMs -> RoPE -> flash attention -> output GEMM
// ---------------------------------------------------------------------------
extern "C" void kernel_launch(void* const* d_in, const int* in_sizes, int n_in,
                              void* d_out, int out_size)
{
    const float* x    = (const float*)d_in[0];
    const float* Wq   = (const float*)d_in[1];
    const float* Wk   = (const float*)d_in[2];
    const float* Wv   = (const float*)d_in[3];
    const float* Wo   = (const float*)d_in[4];
    const float* cosp = (const float*)d_in[5];
    const float* sinp = (const float*)d_in[6];
    float* out = (float*)d_out;

    float *q, *k, *v, *att;
    cudaGetSymbolAddress((void**)&q,   g_q);
    cudaGetSymbolAddress((void**)&k,   g_k);
    cudaGetSymbolAddress((void**)&v,   g_v);
    cudaGetSymbolAddress((void**)&att, g_att);

    cudaFuncSetAttribute(attn_kernel,
                         cudaFuncAttributeMaxDynamicSharedMemorySize, ATTN_SMEM);

    dim3 ggrid(Cc / 128, Mc / 128);  // (8, 32)
    gemm_nt<<<ggrid, 256>>>(x, Wq, q, Mc, Cc, Cc);
    gemm_nt<<<ggrid, 256>>>(x, Wk, k, Mc, Cc, Cc);
    gemm_nt<<<ggrid, 256>>>(x, Wv, v, Mc, Cc, Cc);

    int rope_threads = Bc * Tc * Hc * (HDc / 2);  // 2097152
    rope_kernel<<<rope_threads / 256, 256>>>(q, k, cosp, sinp);

    dim3 agrid(Tc / 64, Hc, Bc);  // (32, 16, 2)
    attn_kernel<<<agrid, 256, ATTN_SMEM>>>(q, k, v, att);

    gemm_nt<<<ggrid, 256>>>(att, Wo, out, Mc, Cc, Cc);
}

// round 14
// speedup vs baseline: 1.4461x; 1.4461x over previous
#include <cuda_runtime.h>
#include <cstdint>
#include <math.h>

// Problem constants
constexpr int Bc = 2;
constexpr int Tc = 2048;
constexpr int Cc = 1024;
constexpr int Hc = 16;
constexpr int HDc = 64;
constexpr int Mc = Bc * Tc;  // 4096 rows

// Scratch (allocation-free rule: __device__ globals)
__device__ float g_q[Bc * Tc * Cc];
__device__ float g_k[Bc * Tc * Cc];
__device__ float g_v[Bc * Tc * Cc];
__device__ float g_att[Bc * Tc * Cc];

// Arch-specific feature gate: tcgen05 only exists on the 'a' targets.
// The harness also emits a generic compute_103 PTX pass which must not see
// tcgen05 instructions — that pass gets the FFMA fallback instead.
#if defined(__CUDA_ARCH_FEAT_SM103_ALL) || defined(__CUDA_ARCH_FEAT_SM100_ALL)
#define HAS_TCGEN05 1
#elif defined(__CUDA_ARCH_HAS_FEATURE__)
#if __CUDA_ARCH_HAS_FEATURE__(SM103_ALL) || __CUDA_ARCH_HAS_FEATURE__(SM100_ALL)
#define HAS_TCGEN05 1
#else
#define HAS_TCGEN05 0
#endif
#else
#define HAS_TCGEN05 0
#endif

// GEMM dynamic smem: 4 tiles (A_hi, B_hi, A_lo, B_lo) of 128x32 fp32 + align pad
constexpr int GEMM_TILE_BYTES = 128 * 32 * 4;           // 16384
constexpr int GEMM_SMEM = 4 * GEMM_TILE_BYTES + 1024;   // 66560

#if HAS_TCGEN05
// ---------------------------------------------------------------------------
// Minimal tcgen05 / mbarrier PTX helpers
// ---------------------------------------------------------------------------
__device__ __forceinline__ uint32_t smem_u32(const void* p) {
    return (uint32_t)__cvta_generic_to_shared(p);
}

__device__ __forceinline__ uint32_t elect_one_pred() {
    uint32_t pred;
    asm volatile(
        "{\n\t.reg .pred p;\n\t"
        "elect.sync _|p, 0xFFFFFFFF;\n\t"
        "selp.b32 %0, 1, 0, p;\n\t}"
        : "=r"(pred));
    return pred;
}

#define TCGEN05_ALLOC(smem_result_addr, nCols) \
    asm volatile("tcgen05.alloc.cta_group::1.sync.aligned.shared::cta.b32 [%0], %1;" \
                 :: "r"((uint32_t)(smem_result_addr)), "r"((uint32_t)(nCols)) : "memory")

#define TCGEN05_DEALLOC(tmem_addr, nCols) \
    asm volatile("tcgen05.dealloc.cta_group::1.sync.aligned.b32 %0, %1;" \
                 :: "r"(tmem_addr), "r"((uint32_t)(nCols)))

#define TCGEN05_RELINQUISH_ALLOC_PERMIT() \
    asm volatile("tcgen05.relinquish_alloc_permit.cta_group::1.sync.aligned;")

#define TCGEN05_COMMIT(mbar_smem_addr) \
    asm volatile("tcgen05.commit.cta_group::1.mbarrier::arrive::one.shared::cluster.b64 [%0];" \
                 :: "r"((uint32_t)(mbar_smem_addr)) : "memory")

#define TCGEN05_FENCE_AFTER() \
    asm volatile("tcgen05.fence::after_thread_sync;" ::: "memory")

#define TCGEN05_FENCE_BEFORE() \
    asm volatile("tcgen05.fence::before_thread_sync;" ::: "memory")

#define TCGEN05_WAIT_LD() \
    asm volatile("tcgen05.wait::ld.sync.aligned;" ::: "memory")

#define FENCE_PROXY_ASYNC_SHARED_CTA() \
    asm volatile("fence.proxy.async.shared::cta;" ::: "memory")

#define MBARRIER_INIT(mbar_smem_addr, count) \
    asm volatile("mbarrier.init.shared.b64 [%0], %1;" \
                 :: "r"((uint32_t)(mbar_smem_addr)), "r"((uint32_t)(count)) : "memory")

#define MBARRIER_WAIT_PARITY(mbar_smem_addr, phase_parity) do { \
    uint32_t _mbar = (uint32_t)(mbar_smem_addr); \
    uint32_t _parity = (uint32_t)(phase_parity); \
    uint32_t _done; \
    asm volatile( \
        "{\n\t.reg .pred p;\n\t" \
        "mbarrier.try_wait.parity.acquire.cta.shared::cta.b64 p, [%1], %2;\n\t" \
        "selp.b32 %0, 1, 0, p;\n\t}" \
        : "=r"(_done) : "r"(_mbar), "r"(_parity) : "memory"); \
    if (!_done) { \
        asm volatile( \
            "{\n\t.reg .pred P1;\n\t" \
            "WAIT_LOOP_%=:\n\t" \
            "mbarrier.try_wait.parity.acquire.cta.shared::cta.b64 P1, [%0], %1, 0x989680;\n\t" \
            "@P1 bra.uni WAIT_DONE_%=;\n\t" \
            "bra.uni WAIT_LOOP_%=;\n\t" \
            "WAIT_DONE_%=:\n\t}" \
            :: "r"(_mbar), "r"(_parity) : "memory"); \
    } \
} while(0)

#define TCGEN05_LD_32X32B_X32(r, tmem_addr) \
    asm volatile( \
        "tcgen05.ld.sync.aligned.32x32b.x32.b32 " \
        "{%0, %1, %2, %3, %4, %5, %6, %7, " \
        " %8, %9, %10, %11, %12, %13, %14, %15, " \
        " %16, %17, %18, %19, %20, %21, %22, %23, " \
        " %24, %25, %26, %27, %28, %29, %30, %31}, [%32];" \
        : "=r"((r)[0]),  "=r"((r)[1]),  "=r"((r)[2]),  "=r"((r)[3]), \
          "=r"((r)[4]),  "=r"((r)[5]),  "=r"((r)[6]),  "=r"((r)[7]), \
          "=r"((r)[8]),  "=r"((r)[9]),  "=r"((r)[10]), "=r"((r)[11]), \
          "=r"((r)[12]), "=r"((r)[13]), "=r"((r)[14]), "=r"((r)[15]), \
          "=r"((r)[16]), "=r"((r)[17]), "=r"((r)[18]), "=r"((r)[19]), \
          "=r"((r)[20]), "=r"((r)[21]), "=r"((r)[22]), "=r"((r)[23]), \
          "=r"((r)[24]), "=r"((r)[25]), "=r"((r)[26]), "=r"((r)[27]), \
          "=r"((r)[28]), "=r"((r)[29]), "=r"((r)[30]), "=r"((r)[31]) \
        : "r"(tmem_addr))

// SW128 K-major smem descriptor: LBO=1, SBO=64, version=1 (Blackwell), layout=SW128
static constexpr uint64_t SMEM_DESC_BASE_SW128 =
    (uint64_t(2)  << 61) | (uint64_t(1) << 46) | (uint64_t(64) << 32) | (uint64_t(1) << 16);

__device__ __forceinline__ uint64_t make_sw128_desc(uint32_t base_addr) {
    return SMEM_DESC_BASE_SW128 | ((uint64_t)(base_addr >> 4) & 0x3FFF);
}

// tf32 SS MMA, cta_group::1, fp32 accumulate
__device__ __forceinline__ void mma_tf32_ss(uint32_t d_tmem, uint64_t a_desc,
                                            uint64_t b_desc, uint32_t idesc,
                                            bool accum) {
    uint32_t en = accum ? 1u : 0u;
    asm volatile(
        "{\n\t.reg .pred p;\n\t"
        "setp.ne.u32 p, %5, 0;\n\t"
        "tcgen05.mma.cta_group::1.kind::tf32 [%0], %1, %2, %3, {%4, %4, %4, %4}, p;\n\t}"
        :: "r"(d_tmem), "l"(a_desc), "l"(b_desc), "r"(idesc), "r"(0u), "r"(en)
        : "memory");
}

// idesc: dtype=F32(1)@[4], atype=TF32(2)@[7], btype=TF32(2)@[10], N/8@[17], M/16@[24]
constexpr uint32_t GEMM_IDESC =
    (1u << 4) | (2u << 7) | (2u << 10) | ((128u / 8u) << 17) | ((128u / 16u) << 24);
#endif  // HAS_TCGEN05

__device__ __forceinline__ uint32_t sw128(uint32_t off) {
    return off ^ ((off >> 3) & 0x70);
}

// tf32 hi part: top 10 mantissa bits kept (exact in tf32); lo = x - hi (exact fp32)
__device__ __forceinline__ float tf32_hi(float x) {
    return __uint_as_float(__float_as_uint(x) & 0xFFFFE000u);
}

// ---------------------------------------------------------------------------
// GEMM: Cm[m,n] = sum_k A[m*K+k] * W[n*K+k]
// sm_103a pass: tcgen05 tf32x3 (precision-split) SS, 128x128 CTA tile,
//   K-chunk 32 floats (SW128), TMEM accumulate, 8-warp LDTM epilogue.
//   D = Ahi*Bhi + Ahi*Blo + Alo*Bhi  -> ~fp32 accuracy (err ~2^-22)
// generic pass (never selected on GB300): FFMA smem-tiled fallback.
// ---------------------------------------------------------------------------
__global__ __launch_bounds__(256) void gemm_tc(
    const float* __restrict__ A, const float* __restrict__ W,
    float* __restrict__ Cm, int Ndim, int Kdim)
{
#if HAS_TCGEN05
    extern __shared__ char dsm_raw[];
    __shared__ uint32_t sTmemPtr;
    __shared__ __align__(8) unsigned long long sMbar;

    // 1024-align the tile region for SW128 descriptors
    char* dsm = (char*)(((uintptr_t)dsm_raw + 1023) & ~(uintptr_t)1023);
    char* sAhi = dsm;
    char* sBhi = dsm + GEMM_TILE_BYTES;
    char* sAlo = dsm + 2 * GEMM_TILE_BYTES;
    char* sBlo = dsm + 3 * GEMM_TILE_BYTES;

    const int tid = threadIdx.x;
    const int wid = tid >> 5;
    const int lid = tid & 31;
    const int bm = blockIdx.y * 128;
    const int bn = blockIdx.x * 128;

    const uint32_t tptr_addr = smem_u32(&sTmemPtr);
    const uint32_t mbar_addr = smem_u32(&sMbar);

    if (wid == 0) {
        TCGEN05_ALLOC(tptr_addr, 128);
    }
    if (tid == 0) MBARRIER_INIT(mbar_addr, 1);
    __syncthreads();
    const uint32_t tmem = sTmemPtr;

    // Load assignment: thread covers one half-row (16 floats = 4 float4s)
    const int lrow = tid >> 1;            // 0..127
    const int lcol = (tid & 1) * 16;      // float offset within 32-float row
    const float* Ap = A + (size_t)(bm + lrow) * Kdim + lcol;
    const float* Bp = W + (size_t)(bn + lrow) * Kdim + lcol;

    const uint64_t adhi = make_sw128_desc(smem_u32(sAhi));
    const uint64_t bdhi = make_sw128_desc(smem_u32(sBhi));
    const uint64_t adlo = make_sw128_desc(smem_u32(sAlo));
    const uint64_t bdlo = make_sw128_desc(smem_u32(sBlo));
    const int nk = Kdim / 32;

    for (int kc = 0; kc < nk; kc++) {
        if (kc > 0) MBARRIER_WAIT_PARITY(mbar_addr, (kc - 1) & 1);

#pragma unroll
        for (int j = 0; j < 4; j++) {
            float4 va = *(const float4*)(Ap + kc * 32 + j * 4);
            float4 vb = *(const float4*)(Bp + kc * 32 + j * 4);
            float4 vah, val, vbh, vbl;
            vah.x = tf32_hi(va.x); val.x = va.x - vah.x;
            vah.y = tf32_hi(va.y); val.y = va.y - vah.y;
            vah.z = tf32_hi(va.z); val.z = va.z - vah.z;
            vah.w = tf32_hi(va.w); val.w = va.w - vah.w;
            vbh.x = tf32_hi(vb.x); vbl.x = vb.x - vbh.x;
            vbh.y = tf32_hi(vb.y); vbl.y = vb.y - vbh.y;
            vbh.z = tf32_hi(vb.z); vbl.z = vb.z - vbh.z;
            vbh.w = tf32_hi(vb.w); vbl.w = vb.w - vbh.w;
            uint32_t off = sw128((uint32_t)(lrow * 128 + (lcol + j * 4) * 4));
            *(float4*)(sAhi + off) = vah;
            *(float4*)(sAlo + off) = val;
            *(float4*)(sBhi + off) = vbh;
            *(float4*)(sBlo + off) = vbl;
        }
        FENCE_PROXY_ASYNC_SHARED_CTA();
        __syncthreads();

        if (wid == 0) {
            if (elect_one_pred()) {
#pragma unroll
                for (int ks = 0; ks < 4; ks++) {
                    // +2 per 8-float (32-byte) K step within the SW128 row
                    bool acc0 = (kc > 0) || (ks > 0);
                    mma_tf32_ss(tmem, adhi + ks * 2, bdhi + ks * 2, GEMM_IDESC, acc0);
                    mma_tf32_ss(tmem, adhi + ks * 2, bdlo + ks * 2, GEMM_IDESC, true);
                    mma_tf32_ss(tmem, adlo + ks * 2, bdhi + ks * 2, GEMM_IDESC, true);
                }
                TCGEN05_COMMIT(mbar_addr);
            }
        }
    }

    MBARRIER_WAIT_PARITY(mbar_addr, (nk - 1) & 1);
    TCGEN05_FENCE_AFTER();

    // Epilogue: warp w -> subpartition (w&3) lanes, column half (w>>2)*64
    {
        const int sub = wid & 3;
        const int cb = (wid >> 2) * 64;
        uint32_t dr[64];
        TCGEN05_LD_32X32B_X32(dr, tmem + cb);
        TCGEN05_LD_32X32B_X32(dr + 32, tmem + cb + 32);
        TCGEN05_WAIT_LD();
        TCGEN05_FENCE_BEFORE();

        float* dst = Cm + (size_t)(bm + sub * 32 + lid) * Ndim + bn + cb;
#pragma unroll
        for (int c = 0; c < 64; c += 4) {
            *(float4*)(dst + c) = make_float4(
                __uint_as_float(dr[c + 0]), __uint_as_float(dr[c + 1]),
                __uint_as_float(dr[c + 2]), __uint_as_float(dr[c + 3]));
        }
    }

    __syncthreads();
    if (wid == 0) {
        TCGEN05_RELINQUISH_ALLOC_PERMIT();
        TCGEN05_DEALLOC(tmem, 128);
    }
#else
    // FFMA fallback for the generic (non-'a') compilation pass. Proven in R4.
    constexpr int GLDS = 132;
    __shared__ float As[8 * GLDS];
    __shared__ float Bs[8 * GLDS];

    const int tid = threadIdx.x;
    const int tx = tid & 15;
    const int ty = tid >> 4;
    const int bm = blockIdx.y * 128;
    const int bn = blockIdx.x * 128;

    const int lr = tid >> 1;
    const int lk = (tid & 1) * 4;
    const float* Ap = A + (size_t)(bm + lr) * Kdim + lk;
    const float* Bp = W + (size_t)(bn + lr) * Kdim + lk;

    float4 a4 = *(const float4*)Ap;
    float4 b4 = *(const float4*)Bp;

    float acc[8][8];
#pragma unroll
    for (int i = 0; i < 8; i++)
#pragma unroll
        for (int j = 0; j < 8; j++) acc[i][j] = 0.f;

    for (int k0 = 0; k0 < Kdim; k0 += 8) {
        As[(lk + 0) * GLDS + lr] = a4.x;
        As[(lk + 1) * GLDS + lr] = a4.y;
        As[(lk + 2) * GLDS + lr] = a4.z;
        As[(lk + 3) * GLDS + lr] = a4.w;
        Bs[(lk + 0) * GLDS + lr] = b4.x;
        Bs[(lk + 1) * GLDS + lr] = b4.y;
        Bs[(lk + 2) * GLDS + lr] = b4.z;
        Bs[(lk + 3) * GLDS + lr] = b4.w;
        __syncthreads();

        if (k0 + 8 < Kdim) {
            a4 = *(const float4*)(Ap + k0 + 8);
            b4 = *(const float4*)(Bp + k0 + 8);
        }

#pragma unroll
        for (int k = 0; k < 8; k++) {
            float4 ar0 = *(const float4*)&As[k * GLDS + ty * 8];
            float4 ar1 = *(const float4*)&As[k * GLDS + ty * 8 + 4];
            float4 br0 = *(const float4*)&Bs[k * GLDS + tx * 8];
            float4 br1 = *(const float4*)&Bs[k * GLDS + tx * 8 + 4];
            float ar[8] = {ar0.x, ar0.y, ar0.z, ar0.w, ar1.x, ar1.y, ar1.z, ar1.w};
            float br[8] = {br0.x, br0.y, br0.z, br0.w, br1.x, br1.y, br1.z, br1.w};
#pragma unroll
            for (int i = 0; i < 8; i++)
#pragma unroll
                for (int j = 0; j < 8; j++)
                    acc[i][j] = fmaf(ar[i], br[j], acc[i][j]);
        }
        __syncthreads();
    }

#pragma unroll
    for (int i = 0; i < 8; i++) {
        float* dst = Cm + (size_t)(bm + ty * 8 + i) * Ndim + bn + tx * 8;
        *(float4*)dst       = make_float4(acc[i][0], acc[i][1], acc[i][2], acc[i][3]);
        *(float4*)(dst + 4) = make_float4(acc[i][4], acc[i][5], acc[i][6], acc[i][7]);
    }
#endif
}

// ---------------------------------------------------------------------------
// RoPE applied in-place to Q and K
// ---------------------------------------------------------------------------
__global__ __launch_bounds__(256) void rope_kernel(
    float* __restrict__ q, float* __restrict__ k,
    const float* __restrict__ cosp, const float* __restrict__ sinp)
{
    int idx = blockIdx.x * blockDim.x + threadIdx.x;
    int i = idx & 31;
    int h = (idx >> 5) & (Hc - 1);
    int t = (idx >> 9) & (Tc - 1);
    int b = idx >> 20;

    float c = cosp[t * 32 + i];
    float s = sinp[t * 32 + i];
    size_t base = ((size_t)(b * Tc + t)) * Cc + h * HDc + 2 * i;

    float2* qp = (float2*)(q + base);
    float2 qq = *qp;
    *qp = make_float2(qq.x * c - qq.y * s, qq.x * s + qq.y * c);

    float2* kp = (float2*)(k + base);
    float2 kk = *kp;
    *kp = make_float2(kk.x * c - kk.y * s, kk.x * s + kk.y * c);
}

// ---------------------------------------------------------------------------
// Causal flash attention, fp32 (unchanged from passing R4 kernel)
// ---------------------------------------------------------------------------
constexpr int ALD = 68;
constexpr int ATTN_SMEM = 3 * 64 * ALD * (int)sizeof(float);  // 52224 B

__global__ __launch_bounds__(256) void attn_kernel(
    const float* __restrict__ Q, const float* __restrict__ K,
    const float* __restrict__ V, float* __restrict__ O)
{
    extern __shared__ float sm[];
    float* Qst = sm;                  // [d][r]
    float* Kst = sm + 64 * ALD;       // [d][j]; aliased as P [col][row] after scores
    float* Vs  = sm + 2 * 64 * ALD;   // [j][dd]

    const int tid = threadIdx.x;
    const int tx = tid & 15;
    const int ty = tid >> 4;
    const int qt = blockIdx.x;
    const int h  = blockIdx.y;
    const int b  = blockIdx.z;
    const int q0 = qt * 64;

    const int lr  = tid >> 2;
    const int ld0 = (tid & 3) * 16;

    {
        const float* src = Q + (size_t)(b * Tc + q0 + lr) * Cc + h * HDc + ld0;
#pragma unroll
        for (int c4 = 0; c4 < 4; c4++) {
            float4 v4 = *(const float4*)(src + c4 * 4);
            Qst[(ld0 + c4 * 4 + 0) * ALD + lr] = v4.x;
            Qst[(ld0 + c4 * 4 + 1) * ALD + lr] = v4.y;
            Qst[(ld0 + c4 * 4 + 2) * ALD + lr] = v4.z;
            Qst[(ld0 + c4 * 4 + 3) * ALD + lr] = v4.w;
        }
    }

    float m_i[4], l_i[4], acc[4][4];
#pragma unroll
    for (int i = 0; i < 4; i++) {
        m_i[i] = -1e30f;
        l_i[i] = 0.f;
#pragma unroll
        for (int j = 0; j < 4; j++) acc[i][j] = 0.f;
    }

    for (int kt = 0; kt <= qt; kt++) {
        __syncthreads();
        {
            const float* ks = K + (size_t)(b * Tc + kt * 64 + lr) * Cc + h * HDc + ld0;
            const float* vs = V + (size_t)(b * Tc + kt * 64 + lr) * Cc + h * HDc + ld0;
#pragma unroll
            for (int c4 = 0; c4 < 4; c4++) {
                float4 kv = *(const float4*)(ks + c4 * 4);
                Kst[(ld0 + c4 * 4 + 0) * ALD + lr] = kv.x;
                Kst[(ld0 + c4 * 4 + 1) * ALD + lr] = kv.y;
                Kst[(ld0 + c4 * 4 + 2) * ALD + lr] = kv.z;
                Kst[(ld0 + c4 * 4 + 3) * ALD + lr] = kv.w;
                float4 vv = *(const float4*)(vs + c4 * 4);
                *(float4*)&Vs[lr * ALD + ld0 + c4 * 4] = vv;
            }
        }
        __syncthreads();

        float s[4][4];
#pragma unroll
        for (int i = 0; i < 4; i++)
#pragma unroll
            for (int j = 0; j < 4; j++) s[i][j] = 0.f;

#pragma unroll 8
        for (int d = 0; d < 64; d++) {
            float4 aq = *(const float4*)&Qst[d * ALD + ty * 4];
            float4 bk = *(const float4*)&Kst[d * ALD + tx * 4];
            float ar[4] = {aq.x, aq.y, aq.z, aq.w};
            float br[4] = {bk.x, bk.y, bk.z, bk.w};
#pragma unroll
            for (int i = 0; i < 4; i++)
#pragma unroll
                for (int j = 0; j < 4; j++)
                    s[i][j] = fmaf(ar[i], br[j], s[i][j]);
        }

        const float scale = 0.125f;
        if (kt == qt) {
#pragma unroll
            for (int i = 0; i < 4; i++)
#pragma unroll
                for (int j = 0; j < 4; j++) {
                    int qr = ty * 4 + i, kc = tx * 4 + j;
                    s[i][j] = (kc <= qr) ? s[i][j] * scale : -1e30f;
                }
        } else {
#pragma unroll
            for (int i = 0; i < 4; i++)
#pragma unroll
                for (int j = 0; j < 4; j++) s[i][j] *= scale;
        }

        float p[4][4];
#pragma unroll
        for (int i = 0; i < 4; i++) {
            float rm = fmaxf(fmaxf(s[i][0], s[i][1]), fmaxf(s[i][2], s[i][3]));
            rm = fmaxf(rm, __shfl_xor_sync(0xffffffffu, rm, 1));
            rm = fmaxf(rm, __shfl_xor_sync(0xffffffffu, rm, 2));
            rm = fmaxf(rm, __shfl_xor_sync(0xffffffffu, rm, 4));
            rm = fmaxf(rm, __shfl_xor_sync(0xffffffffu, rm, 8));
            float mnew = fmaxf(m_i[i], rm);
            float f = __expf(m_i[i] - mnew);
            float rs = 0.f;
#pragma unroll
            for (int j = 0; j < 4; j++) {
                p[i][j] = __expf(s[i][j] - mnew);
                rs += p[i][j];
            }
            rs += __shfl_xor_sync(0xffffffffu, rs, 1);
            rs += __shfl_xor_sync(0xffffffffu, rs, 2);
            rs += __shfl_xor_sync(0xffffffffu, rs, 4);
            rs += __shfl_xor_sync(0xffffffffu, rs, 8);
            l_i[i] = l_i[i] * f + rs;
            m_i[i] = mnew;
#pragma unroll
            for (int j = 0; j < 4; j++) acc[i][j] *= f;
        }

        __syncthreads();
        float* Pst = Kst;
#pragma unroll
        for (int j = 0; j < 4; j++) {
            *(float4*)&Pst[(tx * 4 + j) * ALD + ty * 4] =
                make_float4(p[0][j], p[1][j], p[2][j], p[3][j]);
        }
        __syncthreads();

#pragma unroll 8
        for (int j = 0; j < 64; j++) {
            float4 ap = *(const float4*)&Pst[j * ALD + ty * 4];
            float4 bv = *(const float4*)&Vs[j * ALD + tx * 4];
            float ar[4] = {ap.x, ap.y, ap.z, ap.w};
            float br[4] = {bv.x, bv.y, bv.z, bv.w};
#pragma unroll
            for (int i = 0; i < 4; i++)
#pragma unroll
                for (int jj = 0; jj < 4; jj++)
                    acc[i][jj] = fmaf(ar[i], br[jj], acc[i][jj]);
        }
    }

#pragma unroll
    for (int i = 0; i < 4; i++) {
        float inv = 1.f / l_i[i];
        float* dst = O + (size_t)(b * Tc + q0 + ty * 4 + i) * Cc + h * HDc + tx * 4;
        *(float4*)dst = make_float4(acc[i][0] * inv, acc[i][1] * inv,
                                    acc[i][2] * inv, acc[i][3] * inv);
    }
}

// ---------------------------------------------------------------------------
// Launch: QKV tcgen05 GEMMs -> RoPE -> flash attention -> output tcgen05 GEMM
// ---------------------------------------------------------------------------
extern "C" void kernel_launch(void* const* d_in, const int* in_sizes, int n_in,
                              void* d_out, int out_size)
{
    const float* x    = (const float*)d_in[0];
    const float* Wq   = (const float*)d_in[1];
    const float* Wk   = (const float*)d_in[2];
    const float* Wv   = (const float*)d_in[3];
    const float* Wo   = (const float*)d_in[4];
    const float* cosp = (const float*)d_in[5];
    const float* sinp = (const float*)d_in[6];
    float* out = (float*)d_out;

    float *q, *k, *v, *att;
    cudaGetSymbolAddress((void**)&q,   g_q);
    cudaGetSymbolAddress((void**)&k,   g_k);
    cudaGetSymbolAddress((void**)&v,   g_v);
    cudaGetSymbolAddress((void**)&att, g_att);

    cudaFuncSetAttribute(attn_kernel,
                         cudaFuncAttributeMaxDynamicSharedMemorySize, ATTN_SMEM);
    cudaFuncSetAttribute(gemm_tc,
                         cudaFuncAttributeMaxDynamicSharedMemorySize, GEMM_SMEM);

    dim3 ggrid(Cc / 128, Mc / 128);  // (8, 32)
    gemm_tc<<<ggrid, 256, GEMM_SMEM>>>(x, Wq, q, Cc, Cc);
    gemm_tc<<<ggrid, 256, GEMM_SMEM>>>(x, Wk, k, Cc, Cc);
    gemm_tc<<<ggrid, 256, GEMM_SMEM>>>(x, Wv, v, Cc, Cc);

    int rope_threads = Bc * Tc * Hc * (HDc / 2);
    rope_kernel<<<rope_threads / 256, 256>>>(q, k, cosp, sinp);

    dim3 agrid(Tc / 64, Hc, Bc);  // (32, 16, 2)
    attn_kernel<<<agrid, 256, ATTN_SMEM>>>(q, k, v, att);

    gemm_tc<<<ggrid, 256, GEMM_SMEM>>>(att, Wo, out, Cc, Cc);
}